// round 9
// baseline (speedup 1.0000x reference)
#include <cuda_runtime.h>
#include <cuda_fp16.h>
#include <math.h>

#define NN 20000
#define NE 640000

typedef unsigned long long u64;
typedef unsigned int u32;
typedef unsigned short u16;

// ---------------- scratch (device globals) ----------------
__device__ __align__(16) float g_xenc[NN * 64];
__device__ __align__(16) float g_x1[NN * 64];
__device__ __align__(16) float g_h1[NN * 64];
__device__ __align__(16) float g_Pa[NN * 128];
__device__ __align__(16) float g_Pb[NN * 128];
__device__ __align__(16) float g_nd0[NN * 128];
__device__ __align__(16) float g_nd1[NN * 128];
__device__ __align__(16) float g_msg0[(size_t)NE * 64];

// ---------------- f32x2 helpers ----------------
static __device__ __forceinline__ u64 fma2(u64 a, u64 b, u64 c) {
    u64 d; asm("fma.rn.f32x2 %0,%1,%2,%3;" : "=l"(d) : "l"(a), "l"(b), "l"(c)); return d;
}
static __device__ __forceinline__ u64 add2(u64 a, u64 b) {
    u64 d; asm("add.rn.f32x2 %0,%1,%2;" : "=l"(d) : "l"(a), "l"(b)); return d;
}
static __device__ __forceinline__ u64 mul2(u64 a, u64 b) {
    u64 d; asm("mul.rn.f32x2 %0,%1,%2;" : "=l"(d) : "l"(a), "l"(b)); return d;
}
static __device__ __forceinline__ u64 pack2(float lo, float hi) {
    u64 d; asm("mov.b64 %0,{%1,%2};" : "=l"(d) : "f"(lo), "f"(hi)); return d;
}
static __device__ __forceinline__ void unpack2(u64 a, float& lo, float& hi) {
    asm("mov.b64 {%0,%1},%2;" : "=f"(lo), "=f"(hi) : "l"(a));
}
static __device__ __forceinline__ float wsum(float v) {
#pragma unroll
    for (int o = 16; o; o >>= 1) v += __shfl_xor_sync(0xffffffffu, v, o);
    return v;
}
static __device__ __forceinline__ u32 smem_u32(const void* p) {
    u32 a; asm("{ .reg .u64 t; cvta.to.shared.u64 t, %1; cvt.u32.u64 %0, t; }" : "=r"(a) : "l"(p));
    return a;
}
static __device__ __forceinline__ u32 packh2(float x, float y) {
    __half hx = __float2half_rn(x), hy = __float2half_rn(y);
    return (u32)__half_as_ushort(hx) | ((u32)__half_as_ushort(hy) << 16);
}

#define LDSM4(r0, r1, r2, r3, a)                                             \
    asm volatile("ldmatrix.sync.aligned.m8n8.x4.shared.b16 {%0,%1,%2,%3}, [%4];" \
                 : "=r"(r0), "=r"(r1), "=r"(r2), "=r"(r3) : "r"(a))
#define MMAH(d, a0, a1, a2, a3, b0, b1)                                      \
    asm volatile("mma.sync.aligned.m16n8k16.row.col.f32.f16.f16.f32 "        \
                 "{%0,%1,%2,%3}, {%4,%5,%6,%7}, {%8,%9}, {%0,%1,%2,%3};"     \
                 : "+f"((d)[0]), "+f"((d)[1]), "+f"((d)[2]), "+f"((d)[3])    \
                 : "r"(a0), "r"(a1), "r"(a2), "r"(a3), "r"(b0), "r"(b1))

// ---------------- smem layout (bytes) ----------------
#define SO_W1TH  0         // [128h][64k] fp16, 128B rows, XOR-swizzled (16384)
#define SO_W1TL  16384
#define SO_W2TH  32768     // [64c][128k] fp16, 256B rows, XOR-swizzled (16384)
#define SO_W2TL  49152
#define SO_SB2   65536     // float[64]
#define SO_SEB   65792     // u64[32]
#define SO_SGP   66048
#define SO_SBBP  66304
#define SO_EEW   66560     // u64[512]
#define SO_WARP  70656     // per-warp regions
#define PW_BYTES 12288
#define PO_EAH   0         // [32e][64k] fp16, 128B rows, XOR swz (4096)
#define PO_H     4096      // [32e][128k] fp16, 256B rows, XOR swz (8192)
#define NWARPS_E 12
#define SM_EDGE_BYTES (70656 + NWARPS_E * PW_BYTES)   // 218112

// ---------------- zero accumulators ----------------
__global__ void k_zero() {
    int i = blockIdx.x * blockDim.x + threadIdx.x;
    if (i < NN * 128 / 4) {
        float4 z = make_float4(0.f, 0.f, 0.f, 0.f);
        ((float4*)g_nd0)[i] = z;
        ((float4*)g_nd1)[i] = z;
    }
}

// ---------------- node encoder ----------------
__global__ void __launch_bounds__(256) k_encode(
    const float* __restrict__ x, const float* __restrict__ enc_w,
    const float* __restrict__ enc_b, const float* __restrict__ enc_g,
    const float* __restrict__ enc_bb)
{
    extern __shared__ float sm[];
    for (int i = threadIdx.x; i < 96 * 64; i += blockDim.x) sm[i] = enc_w[i];
    __syncthreads();
    int l = threadIdx.x & 31;
    int warp = (blockIdx.x * blockDim.x + threadIdx.x) >> 5;
    int nwarps = (gridDim.x * blockDim.x) >> 5;
    float b0 = enc_b[l], b1v = enc_b[l + 32];
    float g0 = enc_g[l], g1 = enc_g[l + 32];
    float bb0 = enc_bb[l], bb1 = enc_bb[l + 32];
    for (int n = warp; n < NN; n += nwarps) {
        float xa = x[(size_t)n * 96 + l];
        float xb = x[(size_t)n * 96 + 32 + l];
        float xc = x[(size_t)n * 96 + 64 + l];
        float z0 = b0, z1 = b1v;
#pragma unroll 8
        for (int k = 0; k < 32; k++) {
            float xk = __shfl_sync(0xffffffffu, xa, k);
            z0 = fmaf(xk, sm[k * 64 + l], z0);
            z1 = fmaf(xk, sm[k * 64 + l + 32], z1);
        }
#pragma unroll 8
        for (int k = 0; k < 32; k++) {
            float xk = __shfl_sync(0xffffffffu, xb, k);
            z0 = fmaf(xk, sm[(k + 32) * 64 + l], z0);
            z1 = fmaf(xk, sm[(k + 32) * 64 + l + 32], z1);
        }
#pragma unroll 8
        for (int k = 0; k < 32; k++) {
            float xk = __shfl_sync(0xffffffffu, xc, k);
            z0 = fmaf(xk, sm[(k + 64) * 64 + l], z0);
            z1 = fmaf(xk, sm[(k + 64) * 64 + l + 32], z1);
        }
        float mu = wsum(z0 + z1) * (1.f / 64.f);
        float sq = wsum(z0 * z0 + z1 * z1) * (1.f / 64.f);
        float rs = rsqrtf(sq - mu * mu + 1e-5f);
        g_xenc[n * 64 + l]      = (z0 - mu) * rs * g0 + bb0;
        g_xenc[n * 64 + l + 32] = (z1 - mu) * rs * g1 + bb1;
    }
}

// ---------------- Pa/Pb precompute: 2 nodes per warp ----------------
__global__ void __launch_bounds__(256) k_prep(
    int use_h, const float* __restrict__ w1, const float* __restrict__ b1)
{
    extern __shared__ float sm[];
    for (int i = threadIdx.x; i < 128 * 128; i += blockDim.x) sm[i] = w1[i];
    __syncthreads();
    const float* xin = use_h ? g_h1 : g_xenc;
    int l = threadIdx.x & 31;
    int warp = (blockIdx.x * blockDim.x + threadIdx.x) >> 5;
    int nwarps = (gridDim.x * blockDim.x) >> 5;
    float4 bv = *(const float4*)(b1 + 4 * l);
    for (int n = warp * 2; n < NN; n += nwarps * 2) {
        float xA0 = xin[n * 64 + l],       xA1 = xin[n * 64 + 32 + l];
        float xB0 = xin[(n + 1) * 64 + l], xB1 = xin[(n + 1) * 64 + 32 + l];
        float4 paA = bv, paB = bv;
        float4 pbA = make_float4(0.f, 0.f, 0.f, 0.f);
        float4 pbB = make_float4(0.f, 0.f, 0.f, 0.f);
#pragma unroll 8
        for (int k = 0; k < 32; k++) {
            float kA = __shfl_sync(0xffffffffu, xA0, k);
            float kB = __shfl_sync(0xffffffffu, xB0, k);
            float4 wa = *(const float4*)(sm + k * 128 + 4 * l);
            float4 wb = *(const float4*)(sm + (k + 64) * 128 + 4 * l);
            paA.x = fmaf(kA, wa.x, paA.x); paA.y = fmaf(kA, wa.y, paA.y);
            paA.z = fmaf(kA, wa.z, paA.z); paA.w = fmaf(kA, wa.w, paA.w);
            pbA.x = fmaf(kA, wb.x, pbA.x); pbA.y = fmaf(kA, wb.y, pbA.y);
            pbA.z = fmaf(kA, wb.z, pbA.z); pbA.w = fmaf(kA, wb.w, pbA.w);
            paB.x = fmaf(kB, wa.x, paB.x); paB.y = fmaf(kB, wa.y, paB.y);
            paB.z = fmaf(kB, wa.z, paB.z); paB.w = fmaf(kB, wa.w, paB.w);
            pbB.x = fmaf(kB, wb.x, pbB.x); pbB.y = fmaf(kB, wb.y, pbB.y);
            pbB.z = fmaf(kB, wb.z, pbB.z); pbB.w = fmaf(kB, wb.w, pbB.w);
        }
#pragma unroll 8
        for (int k = 0; k < 32; k++) {
            float kA = __shfl_sync(0xffffffffu, xA1, k);
            float kB = __shfl_sync(0xffffffffu, xB1, k);
            float4 wa = *(const float4*)(sm + (k + 32) * 128 + 4 * l);
            float4 wb = *(const float4*)(sm + (k + 96) * 128 + 4 * l);
            paA.x = fmaf(kA, wa.x, paA.x); paA.y = fmaf(kA, wa.y, paA.y);
            paA.z = fmaf(kA, wa.z, paA.z); paA.w = fmaf(kA, wa.w, paA.w);
            pbA.x = fmaf(kA, wb.x, pbA.x); pbA.y = fmaf(kA, wb.y, pbA.y);
            pbA.z = fmaf(kA, wb.z, pbA.z); pbA.w = fmaf(kA, wb.w, pbA.w);
            paB.x = fmaf(kB, wa.x, paB.x); paB.y = fmaf(kB, wa.y, paB.y);
            paB.z = fmaf(kB, wa.z, paB.z); paB.w = fmaf(kB, wa.w, paB.w);
            pbB.x = fmaf(kB, wb.x, pbB.x); pbB.y = fmaf(kB, wb.y, pbB.y);
            pbB.z = fmaf(kB, wb.z, pbB.z); pbB.w = fmaf(kB, wb.w, pbB.w);
        }
        *(float4*)(g_Pa + (size_t)n * 128 + 4 * l) = paA;
        *(float4*)(g_Pb + (size_t)n * 128 + 4 * l) = pbA;
        *(float4*)(g_Pa + (size_t)(n + 1) * 128 + 4 * l) = paB;
        *(float4*)(g_Pb + (size_t)(n + 1) * 128 + 4 * l) = pbB;
    }
}

// ---------------- mma.sync edge kernel: M=32 per warp, fp16 2-term ----------------
__global__ void __launch_bounds__(384) k_edge(
    int conv, const int* __restrict__ ei, const float* __restrict__ eattr,
    const float* __restrict__ eenc_w, const float* __restrict__ eenc_b,
    const float* __restrict__ ln_g, const float* __restrict__ ln_b,
    const float* __restrict__ w1, const float* __restrict__ w2,
    const float* __restrict__ b2, const float* __restrict__ tptr)
{
    extern __shared__ __align__(1024) char smraw[];
    const u32 sb = smem_u32(smraw);
    int tid = threadIdx.x;
    int wid = tid >> 5, lane = tid & 31;

    u64* seb  = (u64*)(smraw + SO_SEB);
    u64* sgp  = (u64*)(smraw + SO_SGP);
    u64* sbbp = (u64*)(smraw + SO_SBBP);
    u64* eewp = (u64*)(smraw + SO_EEW);
    float* sb2 = (float*)(smraw + SO_SB2);

    // ---- one-time staging: fp16 split weights, XOR bank-swizzle ----
    for (int i = tid; i < 64 * 128; i += 384) {        // W1c^T [h][k]
        int k = i >> 7, h = i & 127;
        float w = w1[(128 + k) * 128 + h];
        __half hh = __float2half_rn(w);
        __half hl = __float2half_rn(w - __half2float(hh));
        int byte = h * 128 + (((k >> 3) ^ (h & 7)) << 4) + ((k & 7) << 1);
        *(u16*)(smraw + SO_W1TH + byte) = __half_as_ushort(hh);
        *(u16*)(smraw + SO_W1TL + byte) = __half_as_ushort(hl);
    }
    for (int i = tid; i < 128 * 64; i += 384) {        // W2^T [c][k]
        int k = i >> 6, c = i & 63;
        float w = w2[k * 64 + c];
        __half hh = __float2half_rn(w);
        __half hl = __float2half_rn(w - __half2float(hh));
        int byte = c * 256 + (((k >> 3) ^ (c & 7)) << 4) + ((k & 7) << 1);
        *(u16*)(smraw + SO_W2TH + byte) = __half_as_ushort(hh);
        *(u16*)(smraw + SO_W2TL + byte) = __half_as_ushort(hl);
    }
    if (conv == 0) {
        for (int i = tid; i < 512; i += 384) eewp[i] = ((const u64*)eenc_w)[i];
        if (tid < 32) seb[tid] = ((const u64*)eenc_b)[tid];
    }
    if (tid < 32) {
        sgp[tid]  = ((const u64*)ln_g)[tid];
        sbbp[tid] = ((const u64*)ln_b)[tid];
    }
    if (tid < 64) sb2[tid] = b2[tid];
    __syncthreads();

    const float t = tptr[0];
    const int* srcp = ei;
    const int* dstp = ei + NE;
    float* ndb = conv ? g_nd1 : g_nd0;

    char* pw_c = smraw + SO_WARP + wid * PW_BYTES;
    const u32 pwb   = sb + SO_WARP + wid * PW_BYTES;
    const u32 eah_b = pwb + PO_EAH;
    const u32 h_b   = pwb + PO_H;

    const int el = lane >> 1, half = lane & 1;
    const int r0 = lane >> 2, tp = lane & 3;
    const int arow = lane & 15, acu = lane >> 4, as7 = lane & 7;
    const int hl = ((lane >> 4) << 3) | (lane & 7);
    const int khalf = (lane >> 3) & 1;
    const int hl7 = hl & 7;

    const int gw = blockIdx.x * NWARPS_E + wid;
    const int nw = gridDim.x * NWARPS_E;
    for (int g = gw; g < NE / 32; g += nw) {
        const int e32 = g * 32;
        // ---------- phase A: edge features + LN -> EA hi (fp16), 2 passes ----------
#pragma unroll
        for (int eo = 0; eo < 32; eo += 16) {
            u64 z[16];
            if (conv == 0) {
                float ar[16];
                const float4* ap = (const float4*)(eattr + (size_t)(e32 + eo + el) * 16);
                *(float4*)&ar[0]  = ap[0]; *(float4*)&ar[4]  = ap[1];
                *(float4*)&ar[8]  = ap[2]; *(float4*)&ar[12] = ap[3];
#pragma unroll
                for (int j = 0; j < 16; j++) z[j] = seb[half * 16 + j];
#pragma unroll
                for (int k = 0; k < 16; k++) {
                    u64 av = pack2(ar[k], ar[k]);
                    const u64* wr_ = eewp + k * 32 + half * 16;
#pragma unroll
                    for (int j = 0; j < 16; j++) z[j] = fma2(av, wr_[j], z[j]);
                }
            } else {
                const u64* mp = (const u64*)(g_msg0 + (size_t)(e32 + eo + el) * 64 + half * 32);
#pragma unroll
                for (int j = 0; j < 16; j++) z[j] = mp[j];
            }
            u64 s2 = 0ull, q2 = 0ull;
#pragma unroll
            for (int j = 0; j < 16; j++) { s2 = add2(s2, z[j]); q2 = fma2(z[j], z[j], q2); }
            float sl, sh2, ql, qh;
            unpack2(s2, sl, sh2); unpack2(q2, ql, qh);
            float ps = sl + sh2, pq = ql + qh;
            ps += __shfl_xor_sync(0xffffffffu, ps, 1);
            pq += __shfl_xor_sync(0xffffffffu, pq, 1);
            float mu = ps * (1.f / 64.f);
            float rs = rsqrtf(pq * (1.f / 64.f) - mu * mu + 1e-5f);
            u64 nmu2 = pack2(-mu, -mu), rs2 = pack2(rs, rs);
            int row = eo + el;
#pragma unroll
            for (int j = 0; j < 16; j++) {
                u64 cen = mul2(add2(z[j], nmu2), rs2);
                u64 v = fma2(cen, sgp[half * 16 + j], sbbp[half * 16 + j]);
                float lo, hi; unpack2(v, lo, hi);
                int ch = half * 32 + 2 * j;
                int byte = row * 128 + (((ch >> 3) ^ (row & 7)) << 4) + ((ch & 7) << 1);
                *(u32*)(pw_c + PO_EAH + byte) = packh2(lo, hi);
            }
        }
        // per-thread edge rows: j = at*2 + rr -> row at*16 + r0 + 8*rr
        int dj[4], sj[4];
#pragma unroll
        for (int at = 0; at < 2; at++)
#pragma unroll
            for (int rr = 0; rr < 2; rr++) {
                int r = at * 16 + r0 + 8 * rr;
                dj[at * 2 + rr] = dstp[e32 + r];
                sj[at * 2 + rr] = srcp[e32 + r];
            }
        __syncwarp();
        // ---------- GEMM1 (n-halves of 64h) + fused epilogue1 ----------
#pragma unroll
        for (int nhalf = 0; nhalf < 2; nhalf++) {
            float d1[2][8][4];
#pragma unroll
            for (int at = 0; at < 2; at++)
#pragma unroll
                for (int nt = 0; nt < 8; nt++)
                    d1[at][nt][0] = d1[at][nt][1] = d1[at][nt][2] = d1[at][nt][3] = 0.f;
#pragma unroll
            for (int kc = 0; kc < 4; kc++) {
                u32 a0[4], a1[4];
                u32 acol = (u32)(((kc * 2 + acu) ^ as7) << 4);
                LDSM4(a0[0], a0[1], a0[2], a0[3], eah_b + (u32)(arow * 128) + acol);
                LDSM4(a1[0], a1[1], a1[2], a1[3], eah_b + (u32)((16 + arow) * 128) + acol);
#pragma unroll
                for (int p = 0; p < 4; p++) {
                    int rowb = nhalf * 64 + p * 16 + hl;
                    u32 bcol = (u32)(((kc * 2 + khalf) ^ hl7) << 4);
                    u32 ba = sb + SO_W1TH + (u32)(rowb * 128) + bcol;
                    u32 bh0, bh1, bh2, bh3, bl0, bl1, bl2, bl3;
                    LDSM4(bh0, bh1, bh2, bh3, ba);
                    LDSM4(bl0, bl1, bl2, bl3, ba + 16384);
                    MMAH(d1[0][2 * p],     a0[0], a0[1], a0[2], a0[3], bh0, bh1);
                    MMAH(d1[0][2 * p],     a0[0], a0[1], a0[2], a0[3], bl0, bl1);
                    MMAH(d1[0][2 * p + 1], a0[0], a0[1], a0[2], a0[3], bh2, bh3);
                    MMAH(d1[0][2 * p + 1], a0[0], a0[1], a0[2], a0[3], bl2, bl3);
                    MMAH(d1[1][2 * p],     a1[0], a1[1], a1[2], a1[3], bh0, bh1);
                    MMAH(d1[1][2 * p],     a1[0], a1[1], a1[2], a1[3], bl0, bl1);
                    MMAH(d1[1][2 * p + 1], a1[0], a1[1], a1[2], a1[3], bh2, bh3);
                    MMAH(d1[1][2 * p + 1], a1[0], a1[1], a1[2], a1[3], bl2, bl3);
                }
            }
            // epilogue1: + Pab, relu, fp16 -> H
#pragma unroll
            for (int hcl = 0; hcl < 4; hcl++) {
                int hc = nhalf * 4 + hcl;
                int cA = 16 * hc + 2 * tp;
#pragma unroll
                for (int at = 0; at < 2; at++)
#pragma unroll
                    for (int rr = 0; rr < 2; rr++) {
                        int j = at * 2 + rr;
                        int r = at * 16 + r0 + 8 * rr;
                        const float* pa = g_Pa + (size_t)dj[j] * 128;
                        const float* pb = g_Pb + (size_t)sj[j] * 128;
                        float2 a1v = *(const float2*)(pa + cA);
                        float2 b1v = *(const float2*)(pb + cA);
                        float2 a2v = *(const float2*)(pa + cA + 8);
                        float2 b2v = *(const float2*)(pb + cA + 8);
                        float v0 = fmaxf(d1[at][2 * hcl][2 * rr]     + a1v.x + b1v.x, 0.f);
                        float v1 = fmaxf(d1[at][2 * hcl][2 * rr + 1] + a1v.y + b1v.y, 0.f);
                        float v2 = fmaxf(d1[at][2 * hcl + 1][2 * rr]     + a2v.x + b2v.x, 0.f);
                        float v3 = fmaxf(d1[at][2 * hcl + 1][2 * rr + 1] + a2v.y + b2v.y, 0.f);
                        int byte0 = r * 256 + (((2 * hc) ^ (r & 7)) << 4) + 4 * tp;
                        int byte1 = r * 256 + (((2 * hc + 1) ^ (r & 7)) << 4) + 4 * tp;
                        *(u32*)(pw_c + PO_H + byte0) = packh2(v0, v1);
                        *(u32*)(pw_c + PO_H + byte1) = packh2(v2, v3);
                    }
            }
        }
        __syncwarp();
        // ---------- GEMM2 (c-halves of 32c) + epilogue2 ----------
#pragma unroll
        for (int chalf = 0; chalf < 2; chalf++) {
            float d2[2][4][4];
#pragma unroll
            for (int at = 0; at < 2; at++)
#pragma unroll
                for (int nt = 0; nt < 4; nt++)
                    d2[at][nt][0] = d2[at][nt][1] = d2[at][nt][2] = d2[at][nt][3] = 0.f;
#pragma unroll
            for (int hc = 0; hc < 8; hc++) {
                u32 h0[4], h1[4];
                u32 acol = (u32)(((hc * 2 + acu) ^ as7) << 4);
                LDSM4(h0[0], h0[1], h0[2], h0[3], h_b + (u32)(arow * 256) + acol);
                LDSM4(h1[0], h1[1], h1[2], h1[3], h_b + (u32)((16 + arow) * 256) + acol);
#pragma unroll
                for (int q = 0; q < 2; q++) {
                    int rowc = chalf * 32 + q * 16 + hl;
                    u32 bcol = (u32)(((hc * 2 + khalf) ^ hl7) << 4);
                    u32 ba = sb + SO_W2TH + (u32)(rowc * 256) + bcol;
                    u32 bh0, bh1, bh2, bh3, bl0, bl1, bl2, bl3;
                    LDSM4(bh0, bh1, bh2, bh3, ba);
                    LDSM4(bl0, bl1, bl2, bl3, ba + 16384);
                    MMAH(d2[0][2 * q],     h0[0], h0[1], h0[2], h0[3], bh0, bh1);
                    MMAH(d2[0][2 * q],     h0[0], h0[1], h0[2], h0[3], bl0, bl1);
                    MMAH(d2[0][2 * q + 1], h0[0], h0[1], h0[2], h0[3], bh2, bh3);
                    MMAH(d2[0][2 * q + 1], h0[0], h0[1], h0[2], h0[3], bl2, bl3);
                    MMAH(d2[1][2 * q],     h1[0], h1[1], h1[2], h1[3], bh0, bh1);
                    MMAH(d2[1][2 * q],     h1[0], h1[1], h1[2], h1[3], bl0, bl1);
                    MMAH(d2[1][2 * q + 1], h1[0], h1[1], h1[2], h1[3], bh2, bh3);
                    MMAH(d2[1][2 * q + 1], h1[0], h1[1], h1[2], h1[3], bl2, bl3);
                }
            }
            // epilogue2: + b2, exp, RED, msg store
#pragma unroll
            for (int at = 0; at < 2; at++)
#pragma unroll
                for (int rr = 0; rr < 2; rr++) {
                    int j = at * 2 + rr;
                    int r = at * 16 + r0 + 8 * rr;
                    int e = e32 + r;
                    float* nd = ndb + (size_t)dj[j] * 128;
#pragma unroll
                    for (int nt = 0; nt < 4; nt++) {
                        int c0 = chalf * 32 + nt * 8 + 2 * tp;
                        float m0 = d2[at][nt][2 * rr]     + sb2[c0];
                        float m1 = d2[at][nt][2 * rr + 1] + sb2[c0 + 1];
                        float E0 = __expf(m0 * t), E1 = __expf(m1 * t);
                        asm volatile("red.global.add.v4.f32 [%0], {%1,%2,%3,%4};"
                                     :: "l"(nd + 2 * c0), "f"(m0 * E0), "f"(E0),
                                        "f"(m1 * E1), "f"(E1) : "memory");
                        if (conv == 0)
                            *(float2*)(g_msg0 + (size_t)e * 64 + c0) = make_float2(m0, m1);
                    }
                }
        }
        __syncwarp();
    }
}

// ---------------- conv0 node finish ----------------
__global__ void __launch_bounds__(256) k_node0(
    const float* __restrict__ wr, const float* __restrict__ lg, const float* __restrict__ lb)
{
    extern __shared__ float sm[];
    for (int i = threadIdx.x; i < 64 * 64; i += blockDim.x) sm[i] = wr[i];
    __syncthreads();
    int l = threadIdx.x & 31;
    int warp = (blockIdx.x * blockDim.x + threadIdx.x) >> 5;
    int nwarps = (gridDim.x * blockDim.x) >> 5;
    float g0 = lg[l], g1 = lg[l + 32], b0 = lb[l], b1v = lb[l + 32];
    for (int n = warp; n < NN; n += nwarps) {
        float xe0 = g_xenc[n * 64 + l], xe1 = g_xenc[n * 64 + 32 + l];
        float r0 = 0.f, r1 = 0.f;
#pragma unroll 8
        for (int k = 0; k < 32; k++) {
            float xk = __shfl_sync(0xffffffffu, xe0, k);
            r0 = fmaf(xk, sm[k * 64 + l], r0);
            r1 = fmaf(xk, sm[k * 64 + l + 32], r1);
        }
#pragma unroll 8
        for (int k = 0; k < 32; k++) {
            float xk = __shfl_sync(0xffffffffu, xe1, k);
            r0 = fmaf(xk, sm[(k + 32) * 64 + l], r0);
            r1 = fmaf(xk, sm[(k + 32) * 64 + l + 32], r1);
        }
        float2 na = *(const float2*)(g_nd0 + (size_t)n * 128 + 2 * l);
        float2 nb = *(const float2*)(g_nd0 + (size_t)n * 128 + 64 + 2 * l);
        float x10 = ((na.y != 0.f) ? na.x / na.y : 0.f) + r0;
        float x11 = ((nb.y != 0.f) ? nb.x / nb.y : 0.f) + r1;
        g_x1[n * 64 + l] = x10;
        g_x1[n * 64 + l + 32] = x11;
        float mu = wsum(x10 + x11) * (1.f / 64.f);
        float sq = wsum(x10 * x10 + x11 * x11) * (1.f / 64.f);
        float rs = rsqrtf(sq - mu * mu + 1e-5f);
        g_h1[n * 64 + l]      = fmaxf((x10 - mu) * rs * g0 + b0, 0.f);
        g_h1[n * 64 + l + 32] = fmaxf((x11 - mu) * rs * g1 + b1v, 0.f);
    }
}

// ---------------- final node kernel ----------------
__global__ void __launch_bounds__(256) k_node1(
    const float* __restrict__ wr, float* __restrict__ out)
{
    extern __shared__ float sm[];
    for (int i = threadIdx.x; i < 64 * 64; i += blockDim.x) sm[i] = wr[i];
    __syncthreads();
    int l = threadIdx.x & 31;
    int warp = (blockIdx.x * blockDim.x + threadIdx.x) >> 5;
    int nwarps = (gridDim.x * blockDim.x) >> 5;
    for (int n = warp; n < NN; n += nwarps) {
        float he0 = g_h1[n * 64 + l], he1 = g_h1[n * 64 + 32 + l];
        float r0 = 0.f, r1 = 0.f;
#pragma unroll 8
        for (int k = 0; k < 32; k++) {
            float xk = __shfl_sync(0xffffffffu, he0, k);
            r0 = fmaf(xk, sm[k * 64 + l], r0);
            r1 = fmaf(xk, sm[k * 64 + l + 32], r1);
        }
#pragma unroll 8
        for (int k = 0; k < 32; k++) {
            float xk = __shfl_sync(0xffffffffu, he1, k);
            r0 = fmaf(xk, sm[(k + 32) * 64 + l], r0);
            r1 = fmaf(xk, sm[(k + 32) * 64 + l + 32], r1);
        }
        float2 na = *(const float2*)(g_nd1 + (size_t)n * 128 + 2 * l);
        float2 nb = *(const float2*)(g_nd1 + (size_t)n * 128 + 64 + 2 * l);
        float a0 = ((na.y != 0.f) ? na.x / na.y : 0.f) + r0;
        float a1 = ((nb.y != 0.f) ? nb.x / nb.y : 0.f) + r1;
        out[n * 64 + l]      = g_x1[n * 64 + l] + a0;
        out[n * 64 + l + 32] = g_x1[n * 64 + l + 32] + a1;
    }
}

extern "C" void kernel_launch(void* const* d_in, const int* in_sizes, int n_in,
                              void* d_out, int out_size)
{
    const float* x       = (const float*)d_in[0];
    const int*   ei      = (const int*)  d_in[1];
    const float* eattr   = (const float*)d_in[2];
    const float* enc_w   = (const float*)d_in[3];
    const float* enc_b   = (const float*)d_in[4];
    const float* enc_g   = (const float*)d_in[5];
    const float* enc_bb  = (const float*)d_in[6];
    const float* eenc_w  = (const float*)d_in[7];
    const float* eenc_b  = (const float*)d_in[8];
    const float* eenc_g  = (const float*)d_in[9];
    const float* eenc_bb = (const float*)d_in[10];
    const float* c0_w1   = (const float*)d_in[11];
    const float* c0_b1   = (const float*)d_in[12];
    const float* c0_w2   = (const float*)d_in[13];
    const float* c0_b2   = (const float*)d_in[14];
    const float* c0_wr   = (const float*)d_in[15];
    const float* c0_t    = (const float*)d_in[16];
    const float* l1_g    = (const float*)d_in[17];
    const float* l1_b    = (const float*)d_in[18];
    const float* l1_eg   = (const float*)d_in[19];
    const float* l1_eb   = (const float*)d_in[20];
    const float* c1_w1   = (const float*)d_in[21];
    const float* c1_b1   = (const float*)d_in[22];
    const float* c1_w2   = (const float*)d_in[23];
    const float* c1_b2   = (const float*)d_in[24];
    const float* c1_wr   = (const float*)d_in[25];
    const float* c1_t    = (const float*)d_in[26];
    float* out = (float*)d_out;

    cudaFuncSetAttribute(k_prep, cudaFuncAttributeMaxDynamicSharedMemorySize, 65536);
    cudaFuncSetAttribute(k_edge, cudaFuncAttributeMaxDynamicSharedMemorySize, SM_EDGE_BYTES);

    k_zero<<<2500, 256>>>();
    k_encode<<<320, 256, 24576>>>(x, enc_w, enc_b, enc_g, enc_bb);
    k_prep<<<444, 256, 65536>>>(0, c0_w1, c0_b1);
    k_edge<<<148, 384, SM_EDGE_BYTES>>>(0, ei, eattr, eenc_w, eenc_b, eenc_g, eenc_bb,
                                        c0_w1, c0_w2, c0_b2, c0_t);
    k_node0<<<320, 256, 16384>>>(c0_wr, l1_g, l1_b);
    k_prep<<<444, 256, 65536>>>(1, c1_w1, c1_b1);
    k_edge<<<148, 384, SM_EDGE_BYTES>>>(1, ei, eattr, eenc_w, eenc_b, l1_eg, l1_eb,
                                        c1_w1, c1_w2, c1_b2, c1_t);
    k_node1<<<320, 256, 16384>>>(c1_wr, out);
}

// round 10
// speedup vs baseline: 1.1389x; 1.1389x over previous
#include <cuda_runtime.h>
#include <cuda_fp16.h>
#include <math.h>

#define NN 20000
#define NE 640000

typedef unsigned long long u64;
typedef unsigned int u32;
typedef unsigned short u16;

// ---------------- scratch (device globals) ----------------
__device__ __align__(16) float g_xenc[NN * 64];
__device__ __align__(16) float g_x1[NN * 64];
__device__ __align__(16) float g_h1[NN * 64];
__device__ __align__(16) float g_Pa[NN * 128];
__device__ __align__(16) float g_Pb[NN * 128];
__device__ __align__(16) float g_nd0[NN * 128];
__device__ __align__(16) float g_nd1[NN * 128];
__device__ __align__(16) float g_msg0[(size_t)NE * 64];

// ---------------- f32x2 helpers ----------------
static __device__ __forceinline__ u64 fma2(u64 a, u64 b, u64 c) {
    u64 d; asm("fma.rn.f32x2 %0,%1,%2,%3;" : "=l"(d) : "l"(a), "l"(b), "l"(c)); return d;
}
static __device__ __forceinline__ u64 add2(u64 a, u64 b) {
    u64 d; asm("add.rn.f32x2 %0,%1,%2;" : "=l"(d) : "l"(a), "l"(b)); return d;
}
static __device__ __forceinline__ u64 mul2(u64 a, u64 b) {
    u64 d; asm("mul.rn.f32x2 %0,%1,%2;" : "=l"(d) : "l"(a), "l"(b)); return d;
}
static __device__ __forceinline__ u64 pack2(float lo, float hi) {
    u64 d; asm("mov.b64 %0,{%1,%2};" : "=l"(d) : "f"(lo), "f"(hi)); return d;
}
static __device__ __forceinline__ void unpack2(u64 a, float& lo, float& hi) {
    asm("mov.b64 {%0,%1},%2;" : "=f"(lo), "=f"(hi) : "l"(a));
}
static __device__ __forceinline__ float wsum(float v) {
#pragma unroll
    for (int o = 16; o; o >>= 1) v += __shfl_xor_sync(0xffffffffu, v, o);
    return v;
}
static __device__ __forceinline__ u32 smem_u32(const void* p) {
    u32 a; asm("{ .reg .u64 t; cvta.to.shared.u64 t, %1; cvt.u32.u64 %0, t; }" : "=r"(a) : "l"(p));
    return a;
}
static __device__ __forceinline__ u32 packh2(float x, float y) {
    __half hx = __float2half_rn(x), hy = __float2half_rn(y);
    return (u32)__half_as_ushort(hx) | ((u32)__half_as_ushort(hy) << 16);
}

#define LDSM4(r0, r1, r2, r3, a)                                             \
    asm volatile("ldmatrix.sync.aligned.m8n8.x4.shared.b16 {%0,%1,%2,%3}, [%4];" \
                 : "=r"(r0), "=r"(r1), "=r"(r2), "=r"(r3) : "r"(a))
#define MMAH(d, a0, a1, a2, a3, b0, b1)                                      \
    asm volatile("mma.sync.aligned.m16n8k16.row.col.f32.f16.f16.f32 "        \
                 "{%0,%1,%2,%3}, {%4,%5,%6,%7}, {%8,%9}, {%0,%1,%2,%3};"     \
                 : "+f"((d)[0]), "+f"((d)[1]), "+f"((d)[2]), "+f"((d)[3])    \
                 : "r"(a0), "r"(a1), "r"(a2), "r"(a3), "r"(b0), "r"(b1))

// ---------------- smem layout (bytes) ----------------
#define SO_W1TH  0         // [128h][64k] fp16, stride 144  (18432)
#define SO_W1TL  18432
#define SO_W2TH  36864     // [64c][128k] fp16, stride 272  (17408)
#define SO_W2TL  54272
#define SO_SB2   71680     // float[64]
#define SO_SEB   71936     // u64[32]
#define SO_SGP   72192
#define SO_SBBP  72448
#define SO_EEW   72704     // u64[512]
#define SO_WARP  76800     // per-warp regions
#define PW_BYTES 3840
#define PO_EAH   0         // [16e][64k] fp16, stride 144 (2304)
#define PO_HB    2304      // 2 slots x 768 (hi only)
#define NWARPS_E 12
#define SM_EDGE_BYTES (76800 + NWARPS_E * PW_BYTES)   // 122880

// ---------------- zero accumulators ----------------
__global__ void k_zero() {
    int i = blockIdx.x * blockDim.x + threadIdx.x;
    if (i < NN * 128 / 4) {
        float4 z = make_float4(0.f, 0.f, 0.f, 0.f);
        ((float4*)g_nd0)[i] = z;
        ((float4*)g_nd1)[i] = z;
    }
}

// ---------------- node encoder ----------------
__global__ void __launch_bounds__(256) k_encode(
    const float* __restrict__ x, const float* __restrict__ enc_w,
    const float* __restrict__ enc_b, const float* __restrict__ enc_g,
    const float* __restrict__ enc_bb)
{
    extern __shared__ float sm[];
    for (int i = threadIdx.x; i < 96 * 64; i += blockDim.x) sm[i] = enc_w[i];
    __syncthreads();
    int l = threadIdx.x & 31;
    int warp = (blockIdx.x * blockDim.x + threadIdx.x) >> 5;
    int nwarps = (gridDim.x * blockDim.x) >> 5;
    float b0 = enc_b[l], b1v = enc_b[l + 32];
    float g0 = enc_g[l], g1 = enc_g[l + 32];
    float bb0 = enc_bb[l], bb1 = enc_bb[l + 32];
    for (int n = warp; n < NN; n += nwarps) {
        float xa = x[(size_t)n * 96 + l];
        float xb = x[(size_t)n * 96 + 32 + l];
        float xc = x[(size_t)n * 96 + 64 + l];
        float z0 = b0, z1 = b1v;
#pragma unroll 8
        for (int k = 0; k < 32; k++) {
            float xk = __shfl_sync(0xffffffffu, xa, k);
            z0 = fmaf(xk, sm[k * 64 + l], z0);
            z1 = fmaf(xk, sm[k * 64 + l + 32], z1);
        }
#pragma unroll 8
        for (int k = 0; k < 32; k++) {
            float xk = __shfl_sync(0xffffffffu, xb, k);
            z0 = fmaf(xk, sm[(k + 32) * 64 + l], z0);
            z1 = fmaf(xk, sm[(k + 32) * 64 + l + 32], z1);
        }
#pragma unroll 8
        for (int k = 0; k < 32; k++) {
            float xk = __shfl_sync(0xffffffffu, xc, k);
            z0 = fmaf(xk, sm[(k + 64) * 64 + l], z0);
            z1 = fmaf(xk, sm[(k + 64) * 64 + l + 32], z1);
        }
        float mu = wsum(z0 + z1) * (1.f / 64.f);
        float sq = wsum(z0 * z0 + z1 * z1) * (1.f / 64.f);
        float rs = rsqrtf(sq - mu * mu + 1e-5f);
        g_xenc[n * 64 + l]      = (z0 - mu) * rs * g0 + bb0;
        g_xenc[n * 64 + l + 32] = (z1 - mu) * rs * g1 + bb1;
    }
}

// ---------------- Pa/Pb precompute: 2 nodes per warp ----------------
__global__ void __launch_bounds__(256) k_prep(
    int use_h, const float* __restrict__ w1, const float* __restrict__ b1)
{
    extern __shared__ float sm[];
    for (int i = threadIdx.x; i < 128 * 128; i += blockDim.x) sm[i] = w1[i];
    __syncthreads();
    const float* xin = use_h ? g_h1 : g_xenc;
    int l = threadIdx.x & 31;
    int warp = (blockIdx.x * blockDim.x + threadIdx.x) >> 5;
    int nwarps = (gridDim.x * blockDim.x) >> 5;
    float4 bv = *(const float4*)(b1 + 4 * l);
    for (int n = warp * 2; n < NN; n += nwarps * 2) {
        float xA0 = xin[n * 64 + l],       xA1 = xin[n * 64 + 32 + l];
        float xB0 = xin[(n + 1) * 64 + l], xB1 = xin[(n + 1) * 64 + 32 + l];
        float4 paA = bv, paB = bv;
        float4 pbA = make_float4(0.f, 0.f, 0.f, 0.f);
        float4 pbB = make_float4(0.f, 0.f, 0.f, 0.f);
#pragma unroll 8
        for (int k = 0; k < 32; k++) {
            float kA = __shfl_sync(0xffffffffu, xA0, k);
            float kB = __shfl_sync(0xffffffffu, xB0, k);
            float4 wa = *(const float4*)(sm + k * 128 + 4 * l);
            float4 wb = *(const float4*)(sm + (k + 64) * 128 + 4 * l);
            paA.x = fmaf(kA, wa.x, paA.x); paA.y = fmaf(kA, wa.y, paA.y);
            paA.z = fmaf(kA, wa.z, paA.z); paA.w = fmaf(kA, wa.w, paA.w);
            pbA.x = fmaf(kA, wb.x, pbA.x); pbA.y = fmaf(kA, wb.y, pbA.y);
            pbA.z = fmaf(kA, wb.z, pbA.z); pbA.w = fmaf(kA, wb.w, pbA.w);
            paB.x = fmaf(kB, wa.x, paB.x); paB.y = fmaf(kB, wa.y, paB.y);
            paB.z = fmaf(kB, wa.z, paB.z); paB.w = fmaf(kB, wa.w, paB.w);
            pbB.x = fmaf(kB, wb.x, pbB.x); pbB.y = fmaf(kB, wb.y, pbB.y);
            pbB.z = fmaf(kB, wb.z, pbB.z); pbB.w = fmaf(kB, wb.w, pbB.w);
        }
#pragma unroll 8
        for (int k = 0; k < 32; k++) {
            float kA = __shfl_sync(0xffffffffu, xA1, k);
            float kB = __shfl_sync(0xffffffffu, xB1, k);
            float4 wa = *(const float4*)(sm + (k + 32) * 128 + 4 * l);
            float4 wb = *(const float4*)(sm + (k + 96) * 128 + 4 * l);
            paA.x = fmaf(kA, wa.x, paA.x); paA.y = fmaf(kA, wa.y, paA.y);
            paA.z = fmaf(kA, wa.z, paA.z); paA.w = fmaf(kA, wa.w, paA.w);
            pbA.x = fmaf(kA, wb.x, pbA.x); pbA.y = fmaf(kA, wb.y, pbA.y);
            pbA.z = fmaf(kA, wb.z, pbA.z); pbA.w = fmaf(kA, wb.w, pbA.w);
            paB.x = fmaf(kB, wa.x, paB.x); paB.y = fmaf(kB, wa.y, paB.y);
            paB.z = fmaf(kB, wa.z, paB.z); paB.w = fmaf(kB, wa.w, paB.w);
            pbB.x = fmaf(kB, wb.x, pbB.x); pbB.y = fmaf(kB, wb.y, pbB.y);
            pbB.z = fmaf(kB, wb.z, pbB.z); pbB.w = fmaf(kB, wb.w, pbB.w);
        }
        *(float4*)(g_Pa + (size_t)n * 128 + 4 * l) = paA;
        *(float4*)(g_Pb + (size_t)n * 128 + 4 * l) = pbA;
        *(float4*)(g_Pa + (size_t)(n + 1) * 128 + 4 * l) = paB;
        *(float4*)(g_Pb + (size_t)(n + 1) * 128 + 4 * l) = pbB;
    }
}

// ---------------- mma.sync edge kernel: R8 structure, fp16 2-term ----------------
__global__ void __launch_bounds__(384) k_edge(
    int conv, const int* __restrict__ ei, const float* __restrict__ eattr,
    const float* __restrict__ eenc_w, const float* __restrict__ eenc_b,
    const float* __restrict__ ln_g, const float* __restrict__ ln_b,
    const float* __restrict__ w1, const float* __restrict__ w2,
    const float* __restrict__ b2, const float* __restrict__ tptr)
{
    extern __shared__ __align__(1024) char smraw[];
    const u32 sb = smem_u32(smraw);
    int tid = threadIdx.x;
    int wid = tid >> 5, lane = tid & 31;

    u64* seb  = (u64*)(smraw + SO_SEB);
    u64* sgp  = (u64*)(smraw + SO_SGP);
    u64* sbbp = (u64*)(smraw + SO_SBBP);
    u64* eewp = (u64*)(smraw + SO_EEW);
    float* sb2 = (float*)(smraw + SO_SB2);

    // ---- one-time staging: fp16 split weights ----
    for (int i = tid; i < 64 * 128; i += 384) {        // W1c^T [h][k], stride 144
        int k = i >> 7, h = i & 127;
        float w = w1[(128 + k) * 128 + h];
        __half hh = __float2half_rn(w);
        __half hl = __float2half_rn(w - __half2float(hh));
        *(u16*)(smraw + SO_W1TH + h * 144 + k * 2) = __half_as_ushort(hh);
        *(u16*)(smraw + SO_W1TL + h * 144 + k * 2) = __half_as_ushort(hl);
    }
    for (int i = tid; i < 128 * 64; i += 384) {        // W2^T [c][k], stride 272
        int k = i >> 6, c = i & 63;
        float w = w2[k * 64 + c];
        __half hh = __float2half_rn(w);
        __half hl = __float2half_rn(w - __half2float(hh));
        *(u16*)(smraw + SO_W2TH + c * 272 + k * 2) = __half_as_ushort(hh);
        *(u16*)(smraw + SO_W2TL + c * 272 + k * 2) = __half_as_ushort(hl);
    }
    if (conv == 0) {
        for (int i = tid; i < 512; i += 384) eewp[i] = ((const u64*)eenc_w)[i];
        if (tid < 32) seb[tid] = ((const u64*)eenc_b)[tid];
    }
    if (tid < 32) {
        sgp[tid]  = ((const u64*)ln_g)[tid];
        sbbp[tid] = ((const u64*)ln_b)[tid];
    }
    if (tid < 64) sb2[tid] = b2[tid];
    __syncthreads();

    const float t = tptr[0];
    const int* srcp = ei;
    const int* dstp = ei + NE;
    float* ndb = conv ? g_nd1 : g_nd0;

    char* pw_c = smraw + SO_WARP + wid * PW_BYTES;
    const u32 pwb   = sb + SO_WARP + wid * PW_BYTES;
    const u32 eah_b = pwb + PO_EAH;
    const u32 hb_b  = pwb + PO_HB;

    const int el = lane >> 1, half = lane & 1;
    const int r0 = lane >> 2, tp = lane & 3;
    const int hl = ((lane >> 4) << 3) | (lane & 7);
    const int khalf = (lane >> 3) & 1;
    const u32 aoff_ea = (u32)((lane & 15) * 144 + (lane >> 4) * 16);
    const u32 boff4_w1 = (u32)(hl * 144 + khalf * 16);
    const u32 boff4_w2 = (u32)(hl * 272 + khalf * 16);
    const u32 aoff_hb = (u32)((lane & 15) * 48 + (lane >> 4) * 16);

    const int gw = blockIdx.x * NWARPS_E + wid;
    const int nw = gridDim.x * NWARPS_E;
    for (int g = gw; g < NE / 16; g += nw) {
        const int e16 = g * 16;
        // ---------- phase A: edge features + LN -> EA (fp16 hi only) ----------
        {
            u64 z[16];
            if (conv == 0) {
                float ar[16];
                const float4* ap = (const float4*)(eattr + (size_t)(e16 + el) * 16);
                *(float4*)&ar[0]  = ap[0]; *(float4*)&ar[4]  = ap[1];
                *(float4*)&ar[8]  = ap[2]; *(float4*)&ar[12] = ap[3];
#pragma unroll
                for (int j = 0; j < 16; j++) z[j] = seb[half * 16 + j];
#pragma unroll
                for (int k = 0; k < 16; k++) {
                    u64 av = pack2(ar[k], ar[k]);
                    const u64* wr_ = eewp + k * 32 + half * 16;
#pragma unroll
                    for (int j = 0; j < 16; j++) z[j] = fma2(av, wr_[j], z[j]);
                }
            } else {
                const u64* mp = (const u64*)(g_msg0 + (size_t)(e16 + el) * 64 + half * 32);
#pragma unroll
                for (int j = 0; j < 16; j++) z[j] = mp[j];
            }
            u64 s2 = 0ull, q2 = 0ull;
#pragma unroll
            for (int j = 0; j < 16; j++) { s2 = add2(s2, z[j]); q2 = fma2(z[j], z[j], q2); }
            float sl, sh2, ql, qh;
            unpack2(s2, sl, sh2); unpack2(q2, ql, qh);
            float ps = sl + sh2, pq = ql + qh;
            ps += __shfl_xor_sync(0xffffffffu, ps, 1);
            pq += __shfl_xor_sync(0xffffffffu, pq, 1);
            float mu = ps * (1.f / 64.f);
            float rs = rsqrtf(pq * (1.f / 64.f) - mu * mu + 1e-5f);
            u64 nmu2 = pack2(-mu, -mu), rs2 = pack2(rs, rs);
#pragma unroll
            for (int j = 0; j < 16; j++) {
                u64 cen = mul2(add2(z[j], nmu2), rs2);
                u64 v = fma2(cen, sgp[half * 16 + j], sbbp[half * 16 + j]);
                float lo, hi; unpack2(v, lo, hi);
                int ch = half * 32 + 2 * j;
                *(u32*)(pw_c + PO_EAH + el * 144 + ch * 2) = packh2(lo, hi);
            }
        }
        // this thread's edge rows (r0 and r0+8)
        const int d0  = dstp[e16 + r0],     s0  = srcp[e16 + r0];
        const int d1v = dstp[e16 + r0 + 8], s1v = srcp[e16 + r0 + 8];
        __syncwarp();
        // ---------- GEMM1: D1[16e][128h] = EA @ W1c^T (fp16 2-term, paired-B) ----------
        float d1[16][4];
#pragma unroll
        for (int nt = 0; nt < 16; nt++) { d1[nt][0] = d1[nt][1] = d1[nt][2] = d1[nt][3] = 0.f; }
#pragma unroll
        for (int kc = 0; kc < 4; kc++) {
            u32 ah0, ah1, ah2, ah3;
            LDSM4(ah0, ah1, ah2, ah3, eah_b + kc * 32 + aoff_ea);
#pragma unroll
            for (int p = 0; p < 8; p++) {
                u32 bh0, bh1, bh2, bh3, bl0, bl1, bl2, bl3;
                u32 baH = sb + SO_W1TH + (u32)(p * 2304 + kc * 32) + boff4_w1;
                LDSM4(bh0, bh1, bh2, bh3, baH);
                LDSM4(bl0, bl1, bl2, bl3, baH + (SO_W1TL - SO_W1TH));
                MMAH(d1[2 * p],     ah0, ah1, ah2, ah3, bh0, bh1);
                MMAH(d1[2 * p],     ah0, ah1, ah2, ah3, bl0, bl1);
                MMAH(d1[2 * p + 1], ah0, ah1, ah2, ah3, bh2, bh3);
                MMAH(d1[2 * p + 1], ah0, ah1, ah2, ah3, bl2, bl3);
            }
        }
        // ---------- fused epilogue1 + GEMM2 (Pab direct from L2, prefetch 1 hc) ----------
        float d2[8][4];
#pragma unroll
        for (int ct = 0; ct < 8; ct++) { d2[ct][0] = d2[ct][1] = d2[ct][2] = d2[ct][3] = 0.f; }
        float2 pf[8];
        {
            int cb = 2 * tp;
            pf[0] = *(const float2*)(g_Pa + (size_t)d0 * 128 + cb);
            pf[1] = *(const float2*)(g_Pb + (size_t)s0 * 128 + cb);
            pf[2] = *(const float2*)(g_Pa + (size_t)d0 * 128 + cb + 8);
            pf[3] = *(const float2*)(g_Pb + (size_t)s0 * 128 + cb + 8);
            pf[4] = *(const float2*)(g_Pa + (size_t)d1v * 128 + cb);
            pf[5] = *(const float2*)(g_Pb + (size_t)s1v * 128 + cb);
            pf[6] = *(const float2*)(g_Pa + (size_t)d1v * 128 + cb + 8);
            pf[7] = *(const float2*)(g_Pb + (size_t)s1v * 128 + cb + 8);
        }
#pragma unroll
        for (int hc = 0; hc < 8; hc++) {
            float2 nf[8];
            if (hc < 7) {
                int cb = (hc + 1) * 16 + 2 * tp;
                nf[0] = *(const float2*)(g_Pa + (size_t)d0 * 128 + cb);
                nf[1] = *(const float2*)(g_Pb + (size_t)s0 * 128 + cb);
                nf[2] = *(const float2*)(g_Pa + (size_t)d0 * 128 + cb + 8);
                nf[3] = *(const float2*)(g_Pb + (size_t)s0 * 128 + cb + 8);
                nf[4] = *(const float2*)(g_Pa + (size_t)d1v * 128 + cb);
                nf[5] = *(const float2*)(g_Pb + (size_t)s1v * 128 + cb);
                nf[6] = *(const float2*)(g_Pa + (size_t)d1v * 128 + cb + 8);
                nf[7] = *(const float2*)(g_Pb + (size_t)s1v * 128 + cb + 8);
            }
            int n0 = 2 * hc, n1 = 2 * hc + 1;
            u32 slot = (hc & 1) ? 768u : 0u;
#pragma unroll
            for (int rr = 0; rr < 2; rr++) {
                int r = r0 + 8 * rr;
                float pAx = pf[4 * rr].x + pf[4 * rr + 1].x;
                float pAy = pf[4 * rr].y + pf[4 * rr + 1].y;
                float pBx = pf[4 * rr + 2].x + pf[4 * rr + 3].x;
                float pBy = pf[4 * rr + 2].y + pf[4 * rr + 3].y;
                float v0 = fmaxf(d1[n0][2 * rr]     + pAx, 0.f);
                float v1 = fmaxf(d1[n0][2 * rr + 1] + pAy, 0.f);
                float v2 = fmaxf(d1[n1][2 * rr]     + pBx, 0.f);
                float v3 = fmaxf(d1[n1][2 * rr + 1] + pBy, 0.f);
                char* hrow = pw_c + PO_HB + slot + r * 48;
                *(u32*)(hrow + 4 * tp)      = packh2(v0, v1);
                *(u32*)(hrow + 16 + 4 * tp) = packh2(v2, v3);
            }
            __syncwarp();
            u32 ah0, ah1, ah2, ah3;
            LDSM4(ah0, ah1, ah2, ah3, hb_b + slot + aoff_hb);
#pragma unroll
            for (int q = 0; q < 4; q++) {
                u32 bh0, bh1, bh2, bh3, bl0, bl1, bl2, bl3;
                u32 baH = sb + SO_W2TH + (u32)(q * 4352 + hc * 32) + boff4_w2;
                LDSM4(bh0, bh1, bh2, bh3, baH);
                LDSM4(bl0, bl1, bl2, bl3, baH + (SO_W2TL - SO_W2TH));
                MMAH(d2[2 * q],     ah0, ah1, ah2, ah3, bh0, bh1);
                MMAH(d2[2 * q],     ah0, ah1, ah2, ah3, bl0, bl1);
                MMAH(d2[2 * q + 1], ah0, ah1, ah2, ah3, bh2, bh3);
                MMAH(d2[2 * q + 1], ah0, ah1, ah2, ah3, bl2, bl3);
            }
            __syncwarp();
            if (hc < 7) {
#pragma unroll
                for (int j = 0; j < 8; j++) pf[j] = nf[j];
            }
        }
        // ---------- epilogue2: + b2, exp, RED, msg store ----------
#pragma unroll
        for (int rr = 0; rr < 2; rr++) {
            int r = r0 + 8 * rr;
            int e = e16 + r;
            int d = rr ? d1v : d0;
            float* nd = ndb + (size_t)d * 128;
#pragma unroll
            for (int ct = 0; ct < 8; ct++) {
                int c0 = 8 * ct + 2 * tp;
                float m0 = d2[ct][2 * rr]     + sb2[c0];
                float m1 = d2[ct][2 * rr + 1] + sb2[c0 + 1];
                float E0 = __expf(m0 * t), E1 = __expf(m1 * t);
                asm volatile("red.global.add.v4.f32 [%0], {%1,%2,%3,%4};"
                             :: "l"(nd + 2 * c0), "f"(m0 * E0), "f"(E0),
                                "f"(m1 * E1), "f"(E1) : "memory");
                if (conv == 0)
                    *(float2*)(g_msg0 + (size_t)e * 64 + c0) = make_float2(m0, m1);
            }
        }
        __syncwarp();
    }
}

// ---------------- conv0 node finish ----------------
__global__ void __launch_bounds__(256) k_node0(
    const float* __restrict__ wr, const float* __restrict__ lg, const float* __restrict__ lb)
{
    extern __shared__ float sm[];
    for (int i = threadIdx.x; i < 64 * 64; i += blockDim.x) sm[i] = wr[i];
    __syncthreads();
    int l = threadIdx.x & 31;
    int warp = (blockIdx.x * blockDim.x + threadIdx.x) >> 5;
    int nwarps = (gridDim.x * blockDim.x) >> 5;
    float g0 = lg[l], g1 = lg[l + 32], b0 = lb[l], b1v = lb[l + 32];
    for (int n = warp; n < NN; n += nwarps) {
        float xe0 = g_xenc[n * 64 + l], xe1 = g_xenc[n * 64 + 32 + l];
        float r0 = 0.f, r1 = 0.f;
#pragma unroll 8
        for (int k = 0; k < 32; k++) {
            float xk = __shfl_sync(0xffffffffu, xe0, k);
            r0 = fmaf(xk, sm[k * 64 + l], r0);
            r1 = fmaf(xk, sm[k * 64 + l + 32], r1);
        }
#pragma unroll 8
        for (int k = 0; k < 32; k++) {
            float xk = __shfl_sync(0xffffffffu, xe1, k);
            r0 = fmaf(xk, sm[(k + 32) * 64 + l], r0);
            r1 = fmaf(xk, sm[(k + 32) * 64 + l + 32], r1);
        }
        float2 na = *(const float2*)(g_nd0 + (size_t)n * 128 + 2 * l);
        float2 nb = *(const float2*)(g_nd0 + (size_t)n * 128 + 64 + 2 * l);
        float x10 = ((na.y != 0.f) ? na.x / na.y : 0.f) + r0;
        float x11 = ((nb.y != 0.f) ? nb.x / nb.y : 0.f) + r1;
        g_x1[n * 64 + l] = x10;
        g_x1[n * 64 + l + 32] = x11;
        float mu = wsum(x10 + x11) * (1.f / 64.f);
        float sq = wsum(x10 * x10 + x11 * x11) * (1.f / 64.f);
        float rs = rsqrtf(sq - mu * mu + 1e-5f);
        g_h1[n * 64 + l]      = fmaxf((x10 - mu) * rs * g0 + b0, 0.f);
        g_h1[n * 64 + l + 32] = fmaxf((x11 - mu) * rs * g1 + b1v, 0.f);
    }
}

// ---------------- final node kernel ----------------
__global__ void __launch_bounds__(256) k_node1(
    const float* __restrict__ wr, float* __restrict__ out)
{
    extern __shared__ float sm[];
    for (int i = threadIdx.x; i < 64 * 64; i += blockDim.x) sm[i] = wr[i];
    __syncthreads();
    int l = threadIdx.x & 31;
    int warp = (blockIdx.x * blockDim.x + threadIdx.x) >> 5;
    int nwarps = (gridDim.x * blockDim.x) >> 5;
    for (int n = warp; n < NN; n += nwarps) {
        float he0 = g_h1[n * 64 + l], he1 = g_h1[n * 64 + 32 + l];
        float r0 = 0.f, r1 = 0.f;
#pragma unroll 8
        for (int k = 0; k < 32; k++) {
            float xk = __shfl_sync(0xffffffffu, he0, k);
            r0 = fmaf(xk, sm[k * 64 + l], r0);
            r1 = fmaf(xk, sm[k * 64 + l + 32], r1);
        }
#pragma unroll 8
        for (int k = 0; k < 32; k++) {
            float xk = __shfl_sync(0xffffffffu, he1, k);
            r0 = fmaf(xk, sm[(k + 32) * 64 + l], r0);
            r1 = fmaf(xk, sm[(k + 32) * 64 + l + 32], r1);
        }
        float2 na = *(const float2*)(g_nd1 + (size_t)n * 128 + 2 * l);
        float2 nb = *(const float2*)(g_nd1 + (size_t)n * 128 + 64 + 2 * l);
        float a0 = ((na.y != 0.f) ? na.x / na.y : 0.f) + r0;
        float a1 = ((nb.y != 0.f) ? nb.x / nb.y : 0.f) + r1;
        out[n * 64 + l]      = g_x1[n * 64 + l] + a0;
        out[n * 64 + l + 32] = g_x1[n * 64 + l + 32] + a1;
    }
}

extern "C" void kernel_launch(void* const* d_in, const int* in_sizes, int n_in,
                              void* d_out, int out_size)
{
    const float* x       = (const float*)d_in[0];
    const int*   ei      = (const int*)  d_in[1];
    const float* eattr   = (const float*)d_in[2];
    const float* enc_w   = (const float*)d_in[3];
    const float* enc_b   = (const float*)d_in[4];
    const float* enc_g   = (const float*)d_in[5];
    const float* enc_bb  = (const float*)d_in[6];
    const float* eenc_w  = (const float*)d_in[7];
    const float* eenc_b  = (const float*)d_in[8];
    const float* eenc_g  = (const float*)d_in[9];
    const float* eenc_bb = (const float*)d_in[10];
    const float* c0_w1   = (const float*)d_in[11];
    const float* c0_b1   = (const float*)d_in[12];
    const float* c0_w2   = (const float*)d_in[13];
    const float* c0_b2   = (const float*)d_in[14];
    const float* c0_wr   = (const float*)d_in[15];
    const float* c0_t    = (const float*)d_in[16];
    const float* l1_g    = (const float*)d_in[17];
    const float* l1_b    = (const float*)d_in[18];
    const float* l1_eg   = (const float*)d_in[19];
    const float* l1_eb   = (const float*)d_in[20];
    const float* c1_w1   = (const float*)d_in[21];
    const float* c1_b1   = (const float*)d_in[22];
    const float* c1_w2   = (const float*)d_in[23];
    const float* c1_b2   = (const float*)d_in[24];
    const float* c1_wr   = (const float*)d_in[25];
    const float* c1_t    = (const float*)d_in[26];
    float* out = (float*)d_out;

    cudaFuncSetAttribute(k_prep, cudaFuncAttributeMaxDynamicSharedMemorySize, 65536);
    cudaFuncSetAttribute(k_edge, cudaFuncAttributeMaxDynamicSharedMemorySize, SM_EDGE_BYTES);

    k_zero<<<2500, 256>>>();
    k_encode<<<320, 256, 24576>>>(x, enc_w, enc_b, enc_g, enc_bb);
    k_prep<<<444, 256, 65536>>>(0, c0_w1, c0_b1);
    k_edge<<<148, 384, SM_EDGE_BYTES>>>(0, ei, eattr, eenc_w, eenc_b, eenc_g, eenc_bb,
                                        c0_w1, c0_w2, c0_b2, c0_t);
    k_node0<<<320, 256, 16384>>>(c0_wr, l1_g, l1_b);
    k_prep<<<444, 256, 65536>>>(1, c1_w1, c1_b1);
    k_edge<<<148, 384, SM_EDGE_BYTES>>>(1, ei, eattr, eenc_w, eenc_b, l1_eg, l1_eb,
                                        c1_w1, c1_w2, c1_b2, c1_t);
    k_node1<<<320, 256, 16384>>>(c1_wr, out);
}

// round 11
// speedup vs baseline: 1.1788x; 1.0350x over previous
#include <cuda_runtime.h>
#include <cuda_fp16.h>
#include <math.h>

#define NN 20000
#define NE 640000

typedef unsigned long long u64;
typedef unsigned int u32;
typedef unsigned short u16;

// ---------------- scratch (device globals) ----------------
__device__ __align__(16) float g_xenc[NN * 64];
__device__ __align__(16) float g_x1[NN * 64];
__device__ __align__(16) float g_h1[NN * 64];
__device__ __align__(16) float g_Pa[NN * 128];
__device__ __align__(16) float g_Pb[NN * 128];
__device__ __align__(16) float g_nd0[NN * 128];
__device__ __align__(16) float g_nd1[NN * 128];
__device__ __align__(16) float g_msg0[(size_t)NE * 64];

// ---------------- f32x2 helpers ----------------
static __device__ __forceinline__ u64 fma2(u64 a, u64 b, u64 c) {
    u64 d; asm("fma.rn.f32x2 %0,%1,%2,%3;" : "=l"(d) : "l"(a), "l"(b), "l"(c)); return d;
}
static __device__ __forceinline__ u64 add2(u64 a, u64 b) {
    u64 d; asm("add.rn.f32x2 %0,%1,%2;" : "=l"(d) : "l"(a), "l"(b)); return d;
}
static __device__ __forceinline__ u64 mul2(u64 a, u64 b) {
    u64 d; asm("mul.rn.f32x2 %0,%1,%2;" : "=l"(d) : "l"(a), "l"(b)); return d;
}
static __device__ __forceinline__ u64 pack2(float lo, float hi) {
    u64 d; asm("mov.b64 %0,{%1,%2};" : "=l"(d) : "f"(lo), "f"(hi)); return d;
}
static __device__ __forceinline__ void unpack2(u64 a, float& lo, float& hi) {
    asm("mov.b64 {%0,%1},%2;" : "=f"(lo), "=f"(hi) : "l"(a));
}
static __device__ __forceinline__ float wsum(float v) {
#pragma unroll
    for (int o = 16; o; o >>= 1) v += __shfl_xor_sync(0xffffffffu, v, o);
    return v;
}
static __device__ __forceinline__ u32 smem_u32(const void* p) {
    u32 a; asm("{ .reg .u64 t; cvta.to.shared.u64 t, %1; cvt.u32.u64 %0, t; }" : "=r"(a) : "l"(p));
    return a;
}
static __device__ __forceinline__ u32 packh2(float x, float y) {
    __half hx = __float2half_rn(x), hy = __float2half_rn(y);
    return (u32)__half_as_ushort(hx) | ((u32)__half_as_ushort(hy) << 16);
}

#define LDSM4(r0, r1, r2, r3, a)                                             \
    asm volatile("ldmatrix.sync.aligned.m8n8.x4.shared.b16 {%0,%1,%2,%3}, [%4];" \
                 : "=r"(r0), "=r"(r1), "=r"(r2), "=r"(r3) : "r"(a))
#define MMAH(d, a0, a1, a2, a3, b0, b1)                                      \
    asm volatile("mma.sync.aligned.m16n8k16.row.col.f32.f16.f16.f32 "        \
                 "{%0,%1,%2,%3}, {%4,%5,%6,%7}, {%8,%9}, {%0,%1,%2,%3};"     \
                 : "+f"((d)[0]), "+f"((d)[1]), "+f"((d)[2]), "+f"((d)[3])    \
                 : "r"(a0), "r"(a1), "r"(a2), "r"(a3), "r"(b0), "r"(b1))

// ---------------- smem layout (bytes) ----------------
#define SO_W1T   0         // [128h][64k] fp16, stride 144  (18432)
#define SO_W2T   18432     // [64c][128k] fp16, stride 272  (17408)
#define SO_SB2   35840     // float[64]
#define SO_SEB   36096     // u64[32]
#define SO_SGP   36352
#define SO_SBBP  36608
#define SO_EEW   36864     // u64[512]
#define SO_WARP  40960     // per-warp regions
#define PW_BYTES 8192
#define PO_EAH   0         // [16e][64k] fp16, stride 144 (2304)
#define PO_HB    2304      // 2 slots x 768 (hi only)
#define PO_NDT   3840      // [8e][136f] f32 (4352)
#define NWARPS_E 12
#define SM_EDGE_BYTES (40960 + NWARPS_E * PW_BYTES)   // 139264

// ---------------- zero accumulators ----------------
__global__ void k_zero() {
    int i = blockIdx.x * blockDim.x + threadIdx.x;
    if (i < NN * 128 / 4) {
        float4 z = make_float4(0.f, 0.f, 0.f, 0.f);
        ((float4*)g_nd0)[i] = z;
        ((float4*)g_nd1)[i] = z;
    }
}

// ---------------- node encoder ----------------
__global__ void __launch_bounds__(256) k_encode(
    const float* __restrict__ x, const float* __restrict__ enc_w,
    const float* __restrict__ enc_b, const float* __restrict__ enc_g,
    const float* __restrict__ enc_bb)
{
    extern __shared__ float sm[];
    for (int i = threadIdx.x; i < 96 * 64; i += blockDim.x) sm[i] = enc_w[i];
    __syncthreads();
    int l = threadIdx.x & 31;
    int warp = (blockIdx.x * blockDim.x + threadIdx.x) >> 5;
    int nwarps = (gridDim.x * blockDim.x) >> 5;
    float b0 = enc_b[l], b1v = enc_b[l + 32];
    float g0 = enc_g[l], g1 = enc_g[l + 32];
    float bb0 = enc_bb[l], bb1 = enc_bb[l + 32];
    for (int n = warp; n < NN; n += nwarps) {
        float xa = x[(size_t)n * 96 + l];
        float xb = x[(size_t)n * 96 + 32 + l];
        float xc = x[(size_t)n * 96 + 64 + l];
        float z0 = b0, z1 = b1v;
#pragma unroll 8
        for (int k = 0; k < 32; k++) {
            float xk = __shfl_sync(0xffffffffu, xa, k);
            z0 = fmaf(xk, sm[k * 64 + l], z0);
            z1 = fmaf(xk, sm[k * 64 + l + 32], z1);
        }
#pragma unroll 8
        for (int k = 0; k < 32; k++) {
            float xk = __shfl_sync(0xffffffffu, xb, k);
            z0 = fmaf(xk, sm[(k + 32) * 64 + l], z0);
            z1 = fmaf(xk, sm[(k + 32) * 64 + l + 32], z1);
        }
#pragma unroll 8
        for (int k = 0; k < 32; k++) {
            float xk = __shfl_sync(0xffffffffu, xc, k);
            z0 = fmaf(xk, sm[(k + 64) * 64 + l], z0);
            z1 = fmaf(xk, sm[(k + 64) * 64 + l + 32], z1);
        }
        float mu = wsum(z0 + z1) * (1.f / 64.f);
        float sq = wsum(z0 * z0 + z1 * z1) * (1.f / 64.f);
        float rs = rsqrtf(sq - mu * mu + 1e-5f);
        g_xenc[n * 64 + l]      = (z0 - mu) * rs * g0 + bb0;
        g_xenc[n * 64 + l + 32] = (z1 - mu) * rs * g1 + bb1;
    }
}

// ---------------- Pa/Pb precompute: 2 nodes per warp ----------------
__global__ void __launch_bounds__(256) k_prep(
    int use_h, const float* __restrict__ w1, const float* __restrict__ b1)
{
    extern __shared__ float sm[];
    for (int i = threadIdx.x; i < 128 * 128; i += blockDim.x) sm[i] = w1[i];
    __syncthreads();
    const float* xin = use_h ? g_h1 : g_xenc;
    int l = threadIdx.x & 31;
    int warp = (blockIdx.x * blockDim.x + threadIdx.x) >> 5;
    int nwarps = (gridDim.x * blockDim.x) >> 5;
    float4 bv = *(const float4*)(b1 + 4 * l);
    for (int n = warp * 2; n < NN; n += nwarps * 2) {
        float xA0 = xin[n * 64 + l],       xA1 = xin[n * 64 + 32 + l];
        float xB0 = xin[(n + 1) * 64 + l], xB1 = xin[(n + 1) * 64 + 32 + l];
        float4 paA = bv, paB = bv;
        float4 pbA = make_float4(0.f, 0.f, 0.f, 0.f);
        float4 pbB = make_float4(0.f, 0.f, 0.f, 0.f);
#pragma unroll 8
        for (int k = 0; k < 32; k++) {
            float kA = __shfl_sync(0xffffffffu, xA0, k);
            float kB = __shfl_sync(0xffffffffu, xB0, k);
            float4 wa = *(const float4*)(sm + k * 128 + 4 * l);
            float4 wb = *(const float4*)(sm + (k + 64) * 128 + 4 * l);
            paA.x = fmaf(kA, wa.x, paA.x); paA.y = fmaf(kA, wa.y, paA.y);
            paA.z = fmaf(kA, wa.z, paA.z); paA.w = fmaf(kA, wa.w, paA.w);
            pbA.x = fmaf(kA, wb.x, pbA.x); pbA.y = fmaf(kA, wb.y, pbA.y);
            pbA.z = fmaf(kA, wb.z, pbA.z); pbA.w = fmaf(kA, wb.w, pbA.w);
            paB.x = fmaf(kB, wa.x, paB.x); paB.y = fmaf(kB, wa.y, paB.y);
            paB.z = fmaf(kB, wa.z, paB.z); paB.w = fmaf(kB, wa.w, paB.w);
            pbB.x = fmaf(kB, wb.x, pbB.x); pbB.y = fmaf(kB, wb.y, pbB.y);
            pbB.z = fmaf(kB, wb.z, pbB.z); pbB.w = fmaf(kB, wb.w, pbB.w);
        }
#pragma unroll 8
        for (int k = 0; k < 32; k++) {
            float kA = __shfl_sync(0xffffffffu, xA1, k);
            float kB = __shfl_sync(0xffffffffu, xB1, k);
            float4 wa = *(const float4*)(sm + (k + 32) * 128 + 4 * l);
            float4 wb = *(const float4*)(sm + (k + 96) * 128 + 4 * l);
            paA.x = fmaf(kA, wa.x, paA.x); paA.y = fmaf(kA, wa.y, paA.y);
            paA.z = fmaf(kA, wa.z, paA.z); paA.w = fmaf(kA, wa.w, paA.w);
            pbA.x = fmaf(kA, wb.x, pbA.x); pbA.y = fmaf(kA, wb.y, pbA.y);
            pbA.z = fmaf(kA, wb.z, pbA.z); pbA.w = fmaf(kA, wb.w, pbA.w);
            paB.x = fmaf(kB, wa.x, paB.x); paB.y = fmaf(kB, wa.y, paB.y);
            paB.z = fmaf(kB, wa.z, paB.z); paB.w = fmaf(kB, wa.w, paB.w);
            pbB.x = fmaf(kB, wb.x, pbB.x); pbB.y = fmaf(kB, wb.y, pbB.y);
            pbB.z = fmaf(kB, wb.z, pbB.z); pbB.w = fmaf(kB, wb.w, pbB.w);
        }
        *(float4*)(g_Pa + (size_t)n * 128 + 4 * l) = paA;
        *(float4*)(g_Pb + (size_t)n * 128 + 4 * l) = pbA;
        *(float4*)(g_Pa + (size_t)(n + 1) * 128 + 4 * l) = paB;
        *(float4*)(g_Pb + (size_t)(n + 1) * 128 + 4 * l) = pbB;
    }
}

// ---------------- mma.sync edge kernel: fp16, 1-term weights, coalesced RED ----------------
__global__ void __launch_bounds__(384) k_edge(
    int conv, const int* __restrict__ ei, const float* __restrict__ eattr,
    const float* __restrict__ eenc_w, const float* __restrict__ eenc_b,
    const float* __restrict__ ln_g, const float* __restrict__ ln_b,
    const float* __restrict__ w1, const float* __restrict__ w2,
    const float* __restrict__ b2, const float* __restrict__ tptr)
{
    extern __shared__ __align__(1024) char smraw[];
    const u32 sb = smem_u32(smraw);
    int tid = threadIdx.x;
    int wid = tid >> 5, lane = tid & 31;

    u64* seb  = (u64*)(smraw + SO_SEB);
    u64* sgp  = (u64*)(smraw + SO_SGP);
    u64* sbbp = (u64*)(smraw + SO_SBBP);
    u64* eewp = (u64*)(smraw + SO_EEW);
    float* sb2 = (float*)(smraw + SO_SB2);

    // ---- one-time staging: fp16 weights (hi only) ----
    for (int i = tid; i < 64 * 128; i += 384) {        // W1c^T [h][k], stride 144
        int k = i >> 7, h = i & 127;
        *(u16*)(smraw + SO_W1T + h * 144 + k * 2) =
            __half_as_ushort(__float2half_rn(w1[(128 + k) * 128 + h]));
    }
    for (int i = tid; i < 128 * 64; i += 384) {        // W2^T [c][k], stride 272
        int k = i >> 6, c = i & 63;
        *(u16*)(smraw + SO_W2T + c * 272 + k * 2) =
            __half_as_ushort(__float2half_rn(w2[k * 64 + c]));
    }
    if (conv == 0) {
        for (int i = tid; i < 512; i += 384) eewp[i] = ((const u64*)eenc_w)[i];
        if (tid < 32) seb[tid] = ((const u64*)eenc_b)[tid];
    }
    if (tid < 32) {
        sgp[tid]  = ((const u64*)ln_g)[tid];
        sbbp[tid] = ((const u64*)ln_b)[tid];
    }
    if (tid < 64) sb2[tid] = b2[tid];
    __syncthreads();

    const float t = tptr[0];
    const int* srcp = ei;
    const int* dstp = ei + NE;
    float* ndb = conv ? g_nd1 : g_nd0;

    char* pw_c = smraw + SO_WARP + wid * PW_BYTES;
    const u32 pwb   = sb + SO_WARP + wid * PW_BYTES;
    const u32 eah_b = pwb + PO_EAH;
    const u32 hb_b  = pwb + PO_HB;
    float* ndt = (float*)(pw_c + PO_NDT);

    const int el = lane >> 1, half = lane & 1;
    const int r0 = lane >> 2, tp = lane & 3;
    const int hl = ((lane >> 4) << 3) | (lane & 7);
    const int khalf = (lane >> 3) & 1;
    const u32 aoff_ea = (u32)((lane & 15) * 144 + (lane >> 4) * 16);
    const u32 boff4_w1 = (u32)(hl * 144 + khalf * 16);
    const u32 boff4_w2 = (u32)(hl * 272 + khalf * 16);
    const u32 aoff_hb = (u32)((lane & 15) * 48 + (lane >> 4) * 16);

    const int gw = blockIdx.x * NWARPS_E + wid;
    const int nw = gridDim.x * NWARPS_E;
    for (int g = gw; g < NE / 16; g += nw) {
        const int e16 = g * 16;
        // ---------- phase A: edge features + LN -> EA (fp16) ----------
        {
            u64 z[16];
            if (conv == 0) {
                float ar[16];
                const float4* ap = (const float4*)(eattr + (size_t)(e16 + el) * 16);
                *(float4*)&ar[0]  = ap[0]; *(float4*)&ar[4]  = ap[1];
                *(float4*)&ar[8]  = ap[2]; *(float4*)&ar[12] = ap[3];
#pragma unroll
                for (int j = 0; j < 16; j++) z[j] = seb[half * 16 + j];
#pragma unroll
                for (int k = 0; k < 16; k++) {
                    u64 av = pack2(ar[k], ar[k]);
                    const u64* wr_ = eewp + k * 32 + half * 16;
#pragma unroll
                    for (int j = 0; j < 16; j++) z[j] = fma2(av, wr_[j], z[j]);
                }
            } else {
                const u64* mp = (const u64*)(g_msg0 + (size_t)(e16 + el) * 64 + half * 32);
#pragma unroll
                for (int j = 0; j < 16; j++) z[j] = mp[j];
            }
            u64 s2 = 0ull, q2 = 0ull;
#pragma unroll
            for (int j = 0; j < 16; j++) { s2 = add2(s2, z[j]); q2 = fma2(z[j], z[j], q2); }
            float sl, sh2, ql, qh;
            unpack2(s2, sl, sh2); unpack2(q2, ql, qh);
            float ps = sl + sh2, pq = ql + qh;
            ps += __shfl_xor_sync(0xffffffffu, ps, 1);
            pq += __shfl_xor_sync(0xffffffffu, pq, 1);
            float mu = ps * (1.f / 64.f);
            float rs = rsqrtf(pq * (1.f / 64.f) - mu * mu + 1e-5f);
            u64 nmu2 = pack2(-mu, -mu), rs2 = pack2(rs, rs);
#pragma unroll
            for (int j = 0; j < 16; j++) {
                u64 cen = mul2(add2(z[j], nmu2), rs2);
                u64 v = fma2(cen, sgp[half * 16 + j], sbbp[half * 16 + j]);
                float lo, hi; unpack2(v, lo, hi);
                int ch = half * 32 + 2 * j;
                *(u32*)(pw_c + PO_EAH + el * 144 + ch * 2) = packh2(lo, hi);
            }
        }
        // this thread's edge rows (r0 and r0+8)
        const int d0  = dstp[e16 + r0],     s0  = srcp[e16 + r0];
        const int d1v = dstp[e16 + r0 + 8], s1v = srcp[e16 + r0 + 8];
        __syncwarp();
        // ---------- GEMM1: D1[16e][128h] = EA @ W1c^T ----------
        float d1[16][4];
#pragma unroll
        for (int nt = 0; nt < 16; nt++) { d1[nt][0] = d1[nt][1] = d1[nt][2] = d1[nt][3] = 0.f; }
#pragma unroll
        for (int kc = 0; kc < 4; kc++) {
            u32 ah0, ah1, ah2, ah3;
            LDSM4(ah0, ah1, ah2, ah3, eah_b + kc * 32 + aoff_ea);
#pragma unroll
            for (int p = 0; p < 8; p++) {
                u32 bh0, bh1, bh2, bh3;
                LDSM4(bh0, bh1, bh2, bh3,
                      sb + SO_W1T + (u32)(p * 2304 + kc * 32) + boff4_w1);
                MMAH(d1[2 * p],     ah0, ah1, ah2, ah3, bh0, bh1);
                MMAH(d1[2 * p + 1], ah0, ah1, ah2, ah3, bh2, bh3);
            }
        }
        // ---------- fused epilogue1 + GEMM2 (Pab direct from L2, prefetch 1 hc) ----------
        float d2[8][4];
#pragma unroll
        for (int ct = 0; ct < 8; ct++) { d2[ct][0] = d2[ct][1] = d2[ct][2] = d2[ct][3] = 0.f; }
        float2 pf[8];
        {
            int cb = 2 * tp;
            pf[0] = *(const float2*)(g_Pa + (size_t)d0 * 128 + cb);
            pf[1] = *(const float2*)(g_Pb + (size_t)s0 * 128 + cb);
            pf[2] = *(const float2*)(g_Pa + (size_t)d0 * 128 + cb + 8);
            pf[3] = *(const float2*)(g_Pb + (size_t)s0 * 128 + cb + 8);
            pf[4] = *(const float2*)(g_Pa + (size_t)d1v * 128 + cb);
            pf[5] = *(const float2*)(g_Pb + (size_t)s1v * 128 + cb);
            pf[6] = *(const float2*)(g_Pa + (size_t)d1v * 128 + cb + 8);
            pf[7] = *(const float2*)(g_Pb + (size_t)s1v * 128 + cb + 8);
        }
#pragma unroll
        for (int hc = 0; hc < 8; hc++) {
            float2 nf[8];
            if (hc < 7) {
                int cb = (hc + 1) * 16 + 2 * tp;
                nf[0] = *(const float2*)(g_Pa + (size_t)d0 * 128 + cb);
                nf[1] = *(const float2*)(g_Pb + (size_t)s0 * 128 + cb);
                nf[2] = *(const float2*)(g_Pa + (size_t)d0 * 128 + cb + 8);
                nf[3] = *(const float2*)(g_Pb + (size_t)s0 * 128 + cb + 8);
                nf[4] = *(const float2*)(g_Pa + (size_t)d1v * 128 + cb);
                nf[5] = *(const float2*)(g_Pb + (size_t)s1v * 128 + cb);
                nf[6] = *(const float2*)(g_Pa + (size_t)d1v * 128 + cb + 8);
                nf[7] = *(const float2*)(g_Pb + (size_t)s1v * 128 + cb + 8);
            }
            int n0 = 2 * hc, n1 = 2 * hc + 1;
            u32 slot = (hc & 1) ? 768u : 0u;
#pragma unroll
            for (int rr = 0; rr < 2; rr++) {
                int r = r0 + 8 * rr;
                float pAx = pf[4 * rr].x + pf[4 * rr + 1].x;
                float pAy = pf[4 * rr].y + pf[4 * rr + 1].y;
                float pBx = pf[4 * rr + 2].x + pf[4 * rr + 3].x;
                float pBy = pf[4 * rr + 2].y + pf[4 * rr + 3].y;
                float v0 = fmaxf(d1[n0][2 * rr]     + pAx, 0.f);
                float v1 = fmaxf(d1[n0][2 * rr + 1] + pAy, 0.f);
                float v2 = fmaxf(d1[n1][2 * rr]     + pBx, 0.f);
                float v3 = fmaxf(d1[n1][2 * rr + 1] + pBy, 0.f);
                char* hrow = pw_c + PO_HB + slot + r * 48;
                *(u32*)(hrow + 4 * tp)      = packh2(v0, v1);
                *(u32*)(hrow + 16 + 4 * tp) = packh2(v2, v3);
            }
            __syncwarp();
            u32 ah0, ah1, ah2, ah3;
            LDSM4(ah0, ah1, ah2, ah3, hb_b + slot + aoff_hb);
#pragma unroll
            for (int q = 0; q < 4; q++) {
                u32 bh0, bh1, bh2, bh3;
                LDSM4(bh0, bh1, bh2, bh3,
                      sb + SO_W2T + (u32)(q * 4352 + hc * 32) + boff4_w2);
                MMAH(d2[2 * q],     ah0, ah1, ah2, ah3, bh0, bh1);
                MMAH(d2[2 * q + 1], ah0, ah1, ah2, ah3, bh2, bh3);
            }
            __syncwarp();
            if (hc < 7) {
#pragma unroll
                for (int j = 0; j < 8; j++) pf[j] = nf[j];
            }
        }
        // ---------- epilogue2: + b2, exp -> smem transpose -> coalesced RED ----------
#pragma unroll
        for (int rr = 0; rr < 2; rr++) {
            int r = r0 + 8 * rr;
            int e = e16 + r;
#pragma unroll
            for (int ct = 0; ct < 8; ct++) {
                int c0 = 8 * ct + 2 * tp;
                float m0 = d2[ct][2 * rr]     + sb2[c0];
                float m1 = d2[ct][2 * rr + 1] + sb2[c0 + 1];
                float E0 = __expf(m0 * t), E1 = __expf(m1 * t);
                *(float4*)(ndt + r0 * 136 + 2 * c0) = make_float4(m0 * E0, E0, m1 * E1, E1);
                if (conv == 0)
                    *(float2*)(g_msg0 + (size_t)e * 64 + c0) = make_float2(m0, m1);
            }
            __syncwarp();
#pragma unroll 4
            for (int eb = 0; eb < 8; eb++) {
                int d = dstp[e16 + 8 * rr + eb];        // warp-uniform broadcast
                float4 v = *(const float4*)(ndt + eb * 136 + 4 * lane);
                asm volatile("red.global.add.v4.f32 [%0], {%1,%2,%3,%4};"
                             :: "l"(ndb + (size_t)d * 128 + 4 * lane),
                                "f"(v.x), "f"(v.y), "f"(v.z), "f"(v.w) : "memory");
            }
            __syncwarp();
        }
    }
}

// ---------------- conv0 node finish ----------------
__global__ void __launch_bounds__(256) k_node0(
    const float* __restrict__ wr, const float* __restrict__ lg, const float* __restrict__ lb)
{
    extern __shared__ float sm[];
    for (int i = threadIdx.x; i < 64 * 64; i += blockDim.x) sm[i] = wr[i];
    __syncthreads();
    int l = threadIdx.x & 31;
    int warp = (blockIdx.x * blockDim.x + threadIdx.x) >> 5;
    int nwarps = (gridDim.x * blockDim.x) >> 5;
    float g0 = lg[l], g1 = lg[l + 32], b0 = lb[l], b1v = lb[l + 32];
    for (int n = warp; n < NN; n += nwarps) {
        float xe0 = g_xenc[n * 64 + l], xe1 = g_xenc[n * 64 + 32 + l];
        float r0 = 0.f, r1 = 0.f;
#pragma unroll 8
        for (int k = 0; k < 32; k++) {
            float xk = __shfl_sync(0xffffffffu, xe0, k);
            r0 = fmaf(xk, sm[k * 64 + l], r0);
            r1 = fmaf(xk, sm[k * 64 + l + 32], r1);
        }
#pragma unroll 8
        for (int k = 0; k < 32; k++) {
            float xk = __shfl_sync(0xffffffffu, xe1, k);
            r0 = fmaf(xk, sm[(k + 32) * 64 + l], r0);
            r1 = fmaf(xk, sm[(k + 32) * 64 + l + 32], r1);
        }
        float2 na = *(const float2*)(g_nd0 + (size_t)n * 128 + 2 * l);
        float2 nb = *(const float2*)(g_nd0 + (size_t)n * 128 + 64 + 2 * l);
        float x10 = ((na.y != 0.f) ? na.x / na.y : 0.f) + r0;
        float x11 = ((nb.y != 0.f) ? nb.x / nb.y : 0.f) + r1;
        g_x1[n * 64 + l] = x10;
        g_x1[n * 64 + l + 32] = x11;
        float mu = wsum(x10 + x11) * (1.f / 64.f);
        float sq = wsum(x10 * x10 + x11 * x11) * (1.f / 64.f);
        float rs = rsqrtf(sq - mu * mu + 1e-5f);
        g_h1[n * 64 + l]      = fmaxf((x10 - mu) * rs * g0 + b0, 0.f);
        g_h1[n * 64 + l + 32] = fmaxf((x11 - mu) * rs * g1 + b1v, 0.f);
    }
}

// ---------------- final node kernel ----------------
__global__ void __launch_bounds__(256) k_node1(
    const float* __restrict__ wr, float* __restrict__ out)
{
    extern __shared__ float sm[];
    for (int i = threadIdx.x; i < 64 * 64; i += blockDim.x) sm[i] = wr[i];
    __syncthreads();
    int l = threadIdx.x & 31;
    int warp = (blockIdx.x * blockDim.x + threadIdx.x) >> 5;
    int nwarps = (gridDim.x * blockDim.x) >> 5;
    for (int n = warp; n < NN; n += nwarps) {
        float he0 = g_h1[n * 64 + l], he1 = g_h1[n * 64 + 32 + l];
        float r0 = 0.f, r1 = 0.f;
#pragma unroll 8
        for (int k = 0; k < 32; k++) {
            float xk = __shfl_sync(0xffffffffu, he0, k);
            r0 = fmaf(xk, sm[k * 64 + l], r0);
            r1 = fmaf(xk, sm[k * 64 + l + 32], r1);
        }
#pragma unroll 8
        for (int k = 0; k < 32; k++) {
            float xk = __shfl_sync(0xffffffffu, he1, k);
            r0 = fmaf(xk, sm[(k + 32) * 64 + l], r0);
            r1 = fmaf(xk, sm[(k + 32) * 64 + l + 32], r1);
        }
        float2 na = *(const float2*)(g_nd1 + (size_t)n * 128 + 2 * l);
        float2 nb = *(const float2*)(g_nd1 + (size_t)n * 128 + 64 + 2 * l);
        float a0 = ((na.y != 0.f) ? na.x / na.y : 0.f) + r0;
        float a1 = ((nb.y != 0.f) ? nb.x / nb.y : 0.f) + r1;
        out[n * 64 + l]      = g_x1[n * 64 + l] + a0;
        out[n * 64 + l + 32] = g_x1[n * 64 + l + 32] + a1;
    }
}

extern "C" void kernel_launch(void* const* d_in, const int* in_sizes, int n_in,
                              void* d_out, int out_size)
{
    const float* x       = (const float*)d_in[0];
    const int*   ei      = (const int*)  d_in[1];
    const float* eattr   = (const float*)d_in[2];
    const float* enc_w   = (const float*)d_in[3];
    const float* enc_b   = (const float*)d_in[4];
    const float* enc_g   = (const float*)d_in[5];
    const float* enc_bb  = (const float*)d_in[6];
    const float* eenc_w  = (const float*)d_in[7];
    const float* eenc_b  = (const float*)d_in[8];
    const float* eenc_g  = (const float*)d_in[9];
    const float* eenc_bb = (const float*)d_in[10];
    const float* c0_w1   = (const float*)d_in[11];
    const float* c0_b1   = (const float*)d_in[12];
    const float* c0_w2   = (const float*)d_in[13];
    const float* c0_b2   = (const float*)d_in[14];
    const float* c0_wr   = (const float*)d_in[15];
    const float* c0_t    = (const float*)d_in[16];
    const float* l1_g    = (const float*)d_in[17];
    const float* l1_b    = (const float*)d_in[18];
    const float* l1_eg   = (const float*)d_in[19];
    const float* l1_eb   = (const float*)d_in[20];
    const float* c1_w1   = (const float*)d_in[21];
    const float* c1_b1   = (const float*)d_in[22];
    const float* c1_w2   = (const float*)d_in[23];
    const float* c1_b2   = (const float*)d_in[24];
    const float* c1_wr   = (const float*)d_in[25];
    const float* c1_t    = (const float*)d_in[26];
    float* out = (float*)d_out;

    cudaFuncSetAttribute(k_prep, cudaFuncAttributeMaxDynamicSharedMemorySize, 65536);
    cudaFuncSetAttribute(k_edge, cudaFuncAttributeMaxDynamicSharedMemorySize, SM_EDGE_BYTES);

    k_zero<<<2500, 256>>>();
    k_encode<<<320, 256, 24576>>>(x, enc_w, enc_b, enc_g, enc_bb);
    k_prep<<<444, 256, 65536>>>(0, c0_w1, c0_b1);
    k_edge<<<148, 384, SM_EDGE_BYTES>>>(0, ei, eattr, eenc_w, eenc_b, eenc_g, eenc_bb,
                                        c0_w1, c0_w2, c0_b2, c0_t);
    k_node0<<<320, 256, 16384>>>(c0_wr, l1_g, l1_b);
    k_prep<<<444, 256, 65536>>>(1, c1_w1, c1_b1);
    k_edge<<<148, 384, SM_EDGE_BYTES>>>(1, ei, eattr, eenc_w, eenc_b, l1_eg, l1_eb,
                                        c1_w1, c1_w2, c1_b2, c1_t);
    k_node1<<<320, 256, 16384>>>(c1_wr, out);
}